// round 2
// baseline (speedup 1.0000x reference)
#include <cuda_runtime.h>
#include <cuda_bf16.h>

// Problem constants
#define BB 4
#define SS 2048
#define DD 1024
#define HH 16
#define HDIM 64

// Intermediate buffers (static device globals: allowed; no runtime alloc)
__device__ float g_q[BB * SS * DD];
__device__ float g_k[BB * SS * DD];
__device__ float g_v[BB * SS * DD];
__device__ float g_ctx[BB * SS * DD];

// ---------------------------------------------------------------------------
// SGEMM: C[M,N] = A[M,K] @ B[K,N] (+ bias[N] if BIAS)
// Block tile 128x128, K-step 8, 256 threads, 8x8 per thread (split fragments).
// ---------------------------------------------------------------------------
template <bool BIAS>
__global__ __launch_bounds__(256)
void sgemm_128x128(const float* __restrict__ A, const float* __restrict__ B,
                   const float* __restrict__ bias, float* __restrict__ C,
                   int M, int N, int K) {
    __shared__ float As[8][128];   // transposed A tile: As[k][m]
    __shared__ float Bs[8][128];   // Bs[k][n]

    const int tid = threadIdx.x;
    const int tx = tid & 15;       // 0..15 (N fragment)
    const int ty = tid >> 4;       // 0..15 (M fragment)
    const int m0 = blockIdx.y * 128;
    const int n0 = blockIdx.x * 128;

    // A load: 128 rows x 8 cols = 256 float4 (one per thread)
    const int la_row = tid >> 1;          // 0..127
    const int la_col = (tid & 1) * 4;     // 0 or 4
    // B load: 8 rows x 128 cols = 256 float4
    const int lb_row = tid >> 5;          // 0..7
    const int lb_col = (tid & 31) * 4;    // 0..124

    const float* Ap = A + (size_t)(m0 + la_row) * K + la_col;
    const float* Bp = B + (size_t)lb_row * N + n0 + lb_col;

    float acc[8][8];
#pragma unroll
    for (int i = 0; i < 8; i++)
#pragma unroll
        for (int j = 0; j < 8; j++) acc[i][j] = 0.f;

    float4 pa = *(const float4*)Ap;
    float4 pb = *(const float4*)Bp;

    const int ntiles = K >> 3;
    for (int t = 0; t < ntiles; t++) {
        As[la_col + 0][la_row] = pa.x;
        As[la_col + 1][la_row] = pa.y;
        As[la_col + 2][la_row] = pa.z;
        As[la_col + 3][la_row] = pa.w;
        *(float4*)&Bs[lb_row][lb_col] = pb;
        __syncthreads();

        if (t + 1 < ntiles) {
            pa = *(const float4*)(Ap + (t + 1) * 8);
            pb = *(const float4*)(Bp + (size_t)(t + 1) * 8 * N);
        }

#pragma unroll
        for (int kk = 0; kk < 8; kk++) {
            float ra[8], rb[8];
            *(float4*)&ra[0] = *(float4*)&As[kk][ty * 4];
            *(float4*)&ra[4] = *(float4*)&As[kk][64 + ty * 4];
            *(float4*)&rb[0] = *(float4*)&Bs[kk][tx * 4];
            *(float4*)&rb[4] = *(float4*)&Bs[kk][64 + tx * 4];
#pragma unroll
            for (int i = 0; i < 8; i++)
#pragma unroll
                for (int j = 0; j < 8; j++) acc[i][j] += ra[i] * rb[j];
        }
        __syncthreads();
    }

    // Epilogue: 4 regions of 4x4, float4 stores
#pragma unroll
    for (int hi = 0; hi < 2; hi++) {
#pragma unroll
        for (int i = 0; i < 4; i++) {
            const int row = m0 + hi * 64 + ty * 4 + i;
#pragma unroll
            for (int hj = 0; hj < 2; hj++) {
                const int col = n0 + hj * 64 + tx * 4;
                float4 v;
                v.x = acc[hi * 4 + i][hj * 4 + 0];
                v.y = acc[hi * 4 + i][hj * 4 + 1];
                v.z = acc[hi * 4 + i][hj * 4 + 2];
                v.w = acc[hi * 4 + i][hj * 4 + 3];
                if (BIAS) {
                    v.x += bias[col + 0];
                    v.y += bias[col + 1];
                    v.z += bias[col + 2];
                    v.w += bias[col + 3];
                }
                *(float4*)&C[(size_t)row * N + col] = v;
            }
        }
    }
}

// ---------------------------------------------------------------------------
// Flash-attention (fp32), 64x64 tiles, head_dim=64, online softmax.
// Causal mask with +1 lookahead: key k allowed iff k <= q + 1.
// smem: Qs[64][64] + Kbuf[64][64] (rotation-swizzled K, reused for P) +
//       Vs[64][64] = 48 KB static.
// ---------------------------------------------------------------------------
__global__ __launch_bounds__(256)
void attn_kernel(const float* __restrict__ Qg, const float* __restrict__ Kg,
                 const float* __restrict__ Vg, float* __restrict__ Ctx) {
    __shared__ float Qs[64 * 64];
    __shared__ float Kbuf[64 * 64];   // K rotated; later reused as P (plain)
    __shared__ float Vs[64 * 64];

    const int q0 = blockIdx.x * 64;
    const int h = blockIdx.y;
    const int b = blockIdx.z;
    const int tid = threadIdx.x;
    const int tx = tid & 15;
    const int ty = tid >> 4;
    const int lrow = tid >> 4;          // load row 0..15 (step 16)
    const int lcol = (tid & 15) * 4;    // load col 0,4,...,60

    const size_t head_off = ((size_t)b * SS) * DD + (size_t)h * HDIM;
    const float* qbase = Qg + head_off + (size_t)q0 * DD;
    const float* kbase = Kg + head_off;
    const float* vbase = Vg + head_off;

    // Load Q tile (plain layout, broadcast reads later)
#pragma unroll
    for (int r = 0; r < 64; r += 16) {
        *(float4*)&Qs[(r + lrow) * 64 + lcol] =
            *(const float4*)&qbase[(size_t)(r + lrow) * DD + lcol];
    }

    float o[4][4];
    float m_i[4], l_i[4];
#pragma unroll
    for (int i = 0; i < 4; i++) {
        m_i[i] = -1e30f;
        l_i[i] = 0.f;
#pragma unroll
        for (int j = 0; j < 4; j++) o[i][j] = 0.f;
    }

    const int ktiles = min(q0 / 64 + 2, SS / 64);

    __syncthreads();

    for (int t = 0; t < ktiles; t++) {
        const int k0 = t * 64;
        const float* kb = kbase + (size_t)k0 * DD;
        const float* vb = vbase + (size_t)k0 * DD;

        // Load K (rotation swizzle: element (row, d) -> Kbuf[row*64 + ((d+row)&63)])
        // and V (plain).
#pragma unroll
        for (int r = 0; r < 64; r += 16) {
            const int krow = r + lrow;
            float4 kv = *(const float4*)&kb[(size_t)krow * DD + lcol];
            Kbuf[krow * 64 + ((lcol + 0 + krow) & 63)] = kv.x;
            Kbuf[krow * 64 + ((lcol + 1 + krow) & 63)] = kv.y;
            Kbuf[krow * 64 + ((lcol + 2 + krow) & 63)] = kv.z;
            Kbuf[krow * 64 + ((lcol + 3 + krow) & 63)] = kv.w;
            *(float4*)&Vs[krow * 64 + lcol] =
                *(const float4*)&vb[(size_t)krow * DD + lcol];
        }
        __syncthreads();

        // S = Q K^T  (4x4 fragment per thread)
        float s[4][4];
#pragma unroll
        for (int i = 0; i < 4; i++)
#pragma unroll
            for (int j = 0; j < 4; j++) s[i][j] = 0.f;

#pragma unroll 8
        for (int d = 0; d < 64; d++) {
            float ra[4], rb[4];
#pragma unroll
            for (int i = 0; i < 4; i++) ra[i] = Qs[(ty * 4 + i) * 64 + d];
#pragma unroll
            for (int j = 0; j < 4; j++) {
                const int kr = tx * 4 + j;
                rb[j] = Kbuf[kr * 64 + ((d + kr) & 63)];
            }
#pragma unroll
            for (int i = 0; i < 4; i++)
#pragma unroll
                for (int j = 0; j < 4; j++) s[i][j] += ra[i] * rb[j];
        }

        // Scale + causal mask (k <= q+1 allowed)
        const bool need_mask = (k0 >= q0);
#pragma unroll
        for (int i = 0; i < 4; i++)
#pragma unroll
            for (int j = 0; j < 4; j++) {
                s[i][j] *= 0.125f;  // 1/sqrt(64)
                if (need_mask && (k0 + tx * 4 + j > q0 + ty * 4 + i + 1))
                    s[i][j] = -1e30f;
            }

        // Online softmax: row stats across the 16 tx-lanes of each row group
        float p[4][4];
        float psum[4];
#pragma unroll
        for (int i = 0; i < 4; i++) {
            float tmax = fmaxf(fmaxf(s[i][0], s[i][1]), fmaxf(s[i][2], s[i][3]));
#pragma unroll
            for (int off = 8; off; off >>= 1)
                tmax = fmaxf(tmax, __shfl_xor_sync(0xffffffffu, tmax, off));
            const float mnew = fmaxf(m_i[i], tmax);
            const float corr = __expf(m_i[i] - mnew);
            float ps = 0.f;
#pragma unroll
            for (int j = 0; j < 4; j++) {
                p[i][j] = __expf(s[i][j] - mnew);
                ps += p[i][j];
            }
#pragma unroll
            for (int off = 8; off; off >>= 1)
                ps += __shfl_xor_sync(0xffffffffu, ps, off);
            l_i[i] = l_i[i] * corr + ps;
            m_i[i] = mnew;
#pragma unroll
            for (int j = 0; j < 4; j++) o[i][j] *= corr;
            psum[i] = ps;
            (void)psum;
        }

        __syncthreads();  // all threads done reading Kbuf (as K)

        // Write P into Kbuf (plain layout)
#pragma unroll
        for (int i = 0; i < 4; i++) {
            float4 pv;
            pv.x = p[i][0]; pv.y = p[i][1]; pv.z = p[i][2]; pv.w = p[i][3];
            *(float4*)&Kbuf[(ty * 4 + i) * 64 + tx * 4] = pv;
        }
        __syncthreads();

        // O += P @ V
#pragma unroll 4
        for (int kk = 0; kk < 64; kk++) {
            float4 v = *(float4*)&Vs[kk * 64 + tx * 4];
#pragma unroll
            for (int i = 0; i < 4; i++) {
                const float pv = Kbuf[(ty * 4 + i) * 64 + kk];
                o[i][0] += pv * v.x;
                o[i][1] += pv * v.y;
                o[i][2] += pv * v.z;
                o[i][3] += pv * v.w;
            }
        }
        __syncthreads();  // protect Kbuf/Vs before next tile's loads
    }

    // Epilogue: normalize and write ctx[b][q][h*64 + col]
    float* cbase = Ctx + head_off + (size_t)q0 * DD;
#pragma unroll
    for (int i = 0; i < 4; i++) {
        const float inv_l = 1.0f / l_i[i];
        float4 v;
        v.x = o[i][0] * inv_l;
        v.y = o[i][1] * inv_l;
        v.z = o[i][2] * inv_l;
        v.w = o[i][3] * inv_l;
        *(float4*)&cbase[(size_t)(ty * 4 + i) * DD + tx * 4] = v;
    }
}

// ---------------------------------------------------------------------------
// kernel_launch
// ---------------------------------------------------------------------------
extern "C" void kernel_launch(void* const* d_in, const int* in_sizes, int n_in,
                              void* d_out, int out_size) {
    (void)in_sizes; (void)n_in; (void)out_size;
    const float* x  = (const float*)d_in[0];
    const float* Wq = (const float*)d_in[1];
    const float* Wk = (const float*)d_in[2];
    const float* Wv = (const float*)d_in[3];
    const float* Wo = (const float*)d_in[4];
    const float* bo = (const float*)d_in[5];
    float* out = (float*)d_out;

    float *q, *k, *v, *ctx;
    cudaGetSymbolAddress((void**)&q, g_q);
    cudaGetSymbolAddress((void**)&k, g_k);
    cudaGetSymbolAddress((void**)&v, g_v);
    cudaGetSymbolAddress((void**)&ctx, g_ctx);

    const int M = BB * SS;  // 8192
    dim3 gemm_grid(DD / 128, M / 128);  // (8, 64)

    sgemm_128x128<false><<<gemm_grid, 256>>>(x, Wq, nullptr, q, M, DD, DD);
    sgemm_128x128<false><<<gemm_grid, 256>>>(x, Wk, nullptr, k, M, DD, DD);
    sgemm_128x128<false><<<gemm_grid, 256>>>(x, Wv, nullptr, v, M, DD, DD);

    dim3 attn_grid(SS / 64, HH, BB);  // (32, 16, 4)
    attn_kernel<<<attn_grid, 256>>>(q, k, v, ctx);

    sgemm_128x128<true><<<gemm_grid, 256>>>(ctx, Wo, bo, out, M, DD, DD);
}

// round 4
// speedup vs baseline: 1.2616x; 1.2616x over previous
#include <cuda_runtime.h>
#include <cuda_bf16.h>
#include <cstdint>

// Problem constants
#define BB 4
#define SS 2048
#define DD 1024
#define HH 16
#define HDIM 64
#define MM (BB * SS)   // 8192

// ---------------------------------------------------------------------------
// Static device scratch (no runtime allocation allowed)
// ---------------------------------------------------------------------------
__device__ float g_q[MM * DD];
__device__ float g_k[MM * DD];
__device__ float g_v[MM * DD];
__device__ float g_ctx[MM * DD];

__device__ __nv_bfloat16 g_xh[MM * DD];
__device__ __nv_bfloat16 g_xl[MM * DD];
__device__ __nv_bfloat16 g_ch[MM * DD];
__device__ __nv_bfloat16 g_cl[MM * DD];
__device__ __nv_bfloat16 g_wh[4][DD * DD];  // transposed W hi: [N][K]
__device__ __nv_bfloat16 g_wl[4][DD * DD];  // transposed W lo: [N][K]

// ---------------------------------------------------------------------------
// PTX helpers (arch-agnostic: cp.async + ldmatrix + mma.sync only)
// ---------------------------------------------------------------------------
__device__ __forceinline__ uint32_t smem_u32(const void* p) {
    return (uint32_t)__cvta_generic_to_shared(p);
}

__device__ __forceinline__ void cp16(uint32_t dst, const void* src) {
    asm volatile("cp.async.cg.shared.global [%0], [%1], 16;" :: "r"(dst), "l"(src));
}

__device__ __forceinline__ void ldsm4(uint32_t& r0, uint32_t& r1, uint32_t& r2,
                                      uint32_t& r3, uint32_t addr) {
    asm volatile("ldmatrix.sync.aligned.m8n8.x4.shared.b16 {%0,%1,%2,%3}, [%4];"
                 : "=r"(r0), "=r"(r1), "=r"(r2), "=r"(r3) : "r"(addr));
}

__device__ __forceinline__ void mma_bf16(float c[4], uint32_t a0, uint32_t a1,
                                         uint32_t a2, uint32_t a3,
                                         uint32_t b0, uint32_t b1) {
    asm volatile(
        "mma.sync.aligned.m16n8k16.row.col.f32.bf16.bf16.f32 "
        "{%0,%1,%2,%3}, {%4,%5,%6,%7}, {%8,%9}, {%0,%1,%2,%3};"
        : "+f"(c[0]), "+f"(c[1]), "+f"(c[2]), "+f"(c[3])
        : "r"(a0), "r"(a1), "r"(a2), "r"(a3), "r"(b0), "r"(b1));
}

// ---------------------------------------------------------------------------
// bf16-split HMMA GEMM: C[M,1024] = A[M,1024] @ W^T[N=1024,K] (+bias)
//   A hi/lo bf16 row-major [M,K]; W hi/lo TRANSPOSED [N,K] row-major.
//   C = Ah*Bh + Ah*Bl + Al*Bh, fp32 accumulate in registers.
// CTA tile 128x128, 8 warps (4m x 2n), warp tile 32x64 via m16n8k16.
// K-chunks of 32, double-buffered cp.async.
// ---------------------------------------------------------------------------
#define KC 32
#define ASTRIDE 40                    // bf16 elems per smem row (80B, conflict-free)
#define OP_ELEMS (128 * ASTRIDE)      // per operand per stage
#define NSTG 2
#define NCHUNK 96                     // 3 passes * (1024/32)
#define GEMM_SMEM (NSTG * 2 * OP_ELEMS * 2)  // 40960 bytes

template <bool BIAS>
__global__ __launch_bounds__(256, 2)
void gemm_mma(const __nv_bfloat16* __restrict__ Ah, const __nv_bfloat16* __restrict__ Al,
              const __nv_bfloat16* __restrict__ Bh, const __nv_bfloat16* __restrict__ Bl,
              const float* __restrict__ bias, float* __restrict__ C) {
    extern __shared__ __align__(16) char dyn_smem[];
    __nv_bfloat16* sm = (__nv_bfloat16*)dyn_smem;

    const int tid = threadIdx.x;
    const int wid = tid >> 5;
    const int lane = tid & 31;
    const int wm = (wid & 3) * 32;        // warp m offset within tile
    const int wn = (wid >> 2) * 64;       // warp n offset within tile
    const int m0 = blockIdx.y * 128;
    const int n0 = blockIdx.x * 128;

    float acc[2][8][4];
#pragma unroll
    for (int i = 0; i < 2; i++)
#pragma unroll
        for (int j = 0; j < 8; j++)
#pragma unroll
            for (int t = 0; t < 4; t++) acc[i][j][t] = 0.f;

    // Per-thread load geometry: 2 segments per operand (512 x 16B per operand)
    const int seg0 = tid, seg1 = tid + 256;
    const int r0 = seg0 >> 2, c0 = (seg0 & 3) * 8;
    const int r1 = seg1 >> 2, c1 = (seg1 & 3) * 8;

    auto load_chunk = [&](int c) {
        const int p = c >> 5;          // 0: Ah*Bh, 1: Ah*Bl, 2: Al*Bh
        const int koff = (c & 31) * KC;
        const __nv_bfloat16* Asrc = (p < 2) ? Ah : Al;
        const __nv_bfloat16* Bsrc = (p == 1) ? Bl : Bh;
        __nv_bfloat16* sa = sm + (c & (NSTG - 1)) * 2 * OP_ELEMS;
        __nv_bfloat16* sb = sa + OP_ELEMS;
        cp16(smem_u32(sa + r0 * ASTRIDE + c0), Asrc + (size_t)(m0 + r0) * DD + koff + c0);
        cp16(smem_u32(sa + r1 * ASTRIDE + c1), Asrc + (size_t)(m0 + r1) * DD + koff + c1);
        cp16(smem_u32(sb + r0 * ASTRIDE + c0), Bsrc + (size_t)(n0 + r0) * DD + koff + c0);
        cp16(smem_u32(sb + r1 * ASTRIDE + c1), Bsrc + (size_t)(n0 + r1) * DD + koff + c1);
        asm volatile("cp.async.commit_group;" ::: "memory");
    };

    // ldmatrix lane address components
    const int a_row = lane & 15;            // row within 16-row A tile
    const int a_col = (lane >> 4) * 8;      // k half
    const int b_row = (lane & 7) + ((lane >> 4) << 3);  // n within 16-row pair
    const int b_col = ((lane >> 3) & 1) * 8;            // k half

    load_chunk(0);

    for (int c = 0; c < NCHUNK; c++) {
        if (c + 1 < NCHUNK) {
            load_chunk(c + 1);
            asm volatile("cp.async.wait_group 1;" ::: "memory");
        } else {
            asm volatile("cp.async.wait_group 0;" ::: "memory");
        }
        __syncthreads();

        const __nv_bfloat16* sa = sm + (c & (NSTG - 1)) * 2 * OP_ELEMS;
        const __nv_bfloat16* sb = sa + OP_ELEMS;

#pragma unroll
        for (int ks = 0; ks < 2; ks++) {   // two k16 steps per chunk
            const int k = ks * 16;
            uint32_t a[2][4];
#pragma unroll
            for (int mt = 0; mt < 2; mt++) {
                uint32_t addr = smem_u32(sa + (wm + mt * 16 + a_row) * ASTRIDE + k + a_col);
                ldsm4(a[mt][0], a[mt][1], a[mt][2], a[mt][3], addr);
            }
            uint32_t b[8][2];
#pragma unroll
            for (int np = 0; np < 4; np++) {  // pairs of n8 tiles
                uint32_t addr = smem_u32(sb + (wn + np * 16 + b_row) * ASTRIDE + k + b_col);
                ldsm4(b[2 * np][0], b[2 * np][1], b[2 * np + 1][0], b[2 * np + 1][1], addr);
            }
#pragma unroll
            for (int mt = 0; mt < 2; mt++)
#pragma unroll
                for (int nt = 0; nt < 8; nt++)
                    mma_bf16(acc[mt][nt], a[mt][0], a[mt][1], a[mt][2], a[mt][3],
                             b[nt][0], b[nt][1]);
        }
        __syncthreads();
    }

    // Epilogue: each mma tile: rows lane/4 and lane/4+8, cols 2*(lane%4)+{0,1}
    const int erow = lane >> 2;
    const int ecol = (lane & 3) * 2;
#pragma unroll
    for (int mt = 0; mt < 2; mt++) {
        const int row = m0 + wm + mt * 16 + erow;
#pragma unroll
        for (int nt = 0; nt < 8; nt++) {
            const int col = n0 + wn + nt * 8 + ecol;
            float2 v0, v1;
            v0.x = acc[mt][nt][0]; v0.y = acc[mt][nt][1];
            v1.x = acc[mt][nt][2]; v1.y = acc[mt][nt][3];
            if (BIAS) {
                v0.x += bias[col]; v0.y += bias[col + 1];
                v1.x += bias[col]; v1.y += bias[col + 1];
            }
            *(float2*)&C[(size_t)row * DD + col] = v0;
            *(float2*)&C[(size_t)(row + 8) * DD + col] = v1;
        }
    }
}

// ---------------------------------------------------------------------------
// Prep kernels: fp32 -> (hi, lo) bf16 split; W transpose+split.
// ---------------------------------------------------------------------------
__global__ __launch_bounds__(256)
void cvt_split_kernel(const float* __restrict__ in, __nv_bfloat16* __restrict__ hi,
                      __nv_bfloat16* __restrict__ lo, int n4) {
    int i = blockIdx.x * blockDim.x + threadIdx.x;
    if (i >= n4) return;
    float4 v = ((const float4*)in)[i];
    __nv_bfloat16 h0 = __float2bfloat16(v.x);
    __nv_bfloat16 h1 = __float2bfloat16(v.y);
    __nv_bfloat16 h2 = __float2bfloat16(v.z);
    __nv_bfloat16 h3 = __float2bfloat16(v.w);
    __nv_bfloat162 hp0; hp0.x = h0; hp0.y = h1;
    __nv_bfloat162 hp1; hp1.x = h2; hp1.y = h3;
    __nv_bfloat162 lp0, lp1;
    lp0.x = __float2bfloat16(v.x - __bfloat162float(h0));
    lp0.y = __float2bfloat16(v.y - __bfloat162float(h1));
    lp1.x = __float2bfloat16(v.z - __bfloat162float(h2));
    lp1.y = __float2bfloat16(v.w - __bfloat162float(h3));
    ((__nv_bfloat162*)hi)[2 * i + 0] = hp0;
    ((__nv_bfloat162*)hi)[2 * i + 1] = hp1;
    ((__nv_bfloat162*)lo)[2 * i + 0] = lp0;
    ((__nv_bfloat162*)lo)[2 * i + 1] = lp1;
}

__global__ __launch_bounds__(256)
void wsplit_t_kernel(const float* __restrict__ W, __nv_bfloat16* __restrict__ Th,
                     __nv_bfloat16* __restrict__ Tl) {
    __shared__ float t[32][33];
    const int bx = blockIdx.x * 32;
    const int by = blockIdx.y * 32;
    const int x = bx + threadIdx.x;
#pragma unroll
    for (int j = threadIdx.y; j < 32; j += 8)
        t[j][threadIdx.x] = W[(size_t)(by + j) * DD + x];
    __syncthreads();
    const int xo = by + threadIdx.x;
#pragma unroll
    for (int j = threadIdx.y; j < 32; j += 8) {
        float v = t[threadIdx.x][j];
        __nv_bfloat16 h = __float2bfloat16(v);
        Th[(size_t)(bx + j) * DD + xo] = h;
        Tl[(size_t)(bx + j) * DD + xo] = __float2bfloat16(v - __bfloat162float(h));
    }
}

// ---------------------------------------------------------------------------
// Flash-attention (fp32) — unchanged from the passing baseline.
// ---------------------------------------------------------------------------
__global__ __launch_bounds__(256)
void attn_kernel(const float* __restrict__ Qg, const float* __restrict__ Kg,
                 const float* __restrict__ Vg, float* __restrict__ Ctx) {
    __shared__ float Qs[64 * 64];
    __shared__ float Kbuf[64 * 64];
    __shared__ float Vs[64 * 64];

    const int q0 = blockIdx.x * 64;
    const int h = blockIdx.y;
    const int b = blockIdx.z;
    const int tid = threadIdx.x;
    const int tx = tid & 15;
    const int ty = tid >> 4;
    const int lrow = tid >> 4;
    const int lcol = (tid & 15) * 4;

    const size_t head_off = ((size_t)b * SS) * DD + (size_t)h * HDIM;
    const float* qbase = Qg + head_off + (size_t)q0 * DD;
    const float* kbase = Kg + head_off;
    const float* vbase = Vg + head_off;

#pragma unroll
    for (int r = 0; r < 64; r += 16) {
        *(float4*)&Qs[(r + lrow) * 64 + lcol] =
            *(const float4*)&qbase[(size_t)(r + lrow) * DD + lcol];
    }

    float o[4][4];
    float m_i[4], l_i[4];
#pragma unroll
    for (int i = 0; i < 4; i++) {
        m_i[i] = -1e30f;
        l_i[i] = 0.f;
#pragma unroll
        for (int j = 0; j < 4; j++) o[i][j] = 0.f;
    }

    const int ktiles = min(q0 / 64 + 2, SS / 64);
    __syncthreads();

    for (int t = 0; t < ktiles; t++) {
        const int k0 = t * 64;
        const float* kb = kbase + (size_t)k0 * DD;
        const float* vb = vbase + (size_t)k0 * DD;

#pragma unroll
        for (int r = 0; r < 64; r += 16) {
            const int krow = r + lrow;
            float4 kv = *(const float4*)&kb[(size_t)krow * DD + lcol];
            Kbuf[krow * 64 + ((lcol + 0 + krow) & 63)] = kv.x;
            Kbuf[krow * 64 + ((lcol + 1 + krow) & 63)] = kv.y;
            Kbuf[krow * 64 + ((lcol + 2 + krow) & 63)] = kv.z;
            Kbuf[krow * 64 + ((lcol + 3 + krow) & 63)] = kv.w;
            *(float4*)&Vs[krow * 64 + lcol] =
                *(const float4*)&vb[(size_t)krow * DD + lcol];
        }
        __syncthreads();

        float s[4][4];
#pragma unroll
        for (int i = 0; i < 4; i++)
#pragma unroll
            for (int j = 0; j < 4; j++) s[i][j] = 0.f;

#pragma unroll 8
        for (int d = 0; d < 64; d++) {
            float ra[4], rb[4];
#pragma unroll
            for (int i = 0; i < 4; i++) ra[i] = Qs[(ty * 4 + i) * 64 + d];
#pragma unroll
            for (int j = 0; j < 4; j++) {
                const int kr = tx * 4 + j;
                rb[j] = Kbuf[kr * 64 + ((d + kr) & 63)];
            }
#pragma unroll
            for (int i = 0; i < 4; i++)
#pragma unroll
                for (int j = 0; j < 4; j++) s[i][j] += ra[i] * rb[j];
        }

        const bool need_mask = (k0 >= q0);
#pragma unroll
        for (int i = 0; i < 4; i++)
#pragma unroll
            for (int j = 0; j < 4; j++) {
                s[i][j] *= 0.125f;
                if (need_mask && (k0 + tx * 4 + j > q0 + ty * 4 + i + 1))
                    s[i][j] = -1e30f;
            }

        float p[4][4];
#pragma unroll
        for (int i = 0; i < 4; i++) {
            float tmax = fmaxf(fmaxf(s[i][0], s[i][1]), fmaxf(s[i][2], s[i][3]));
#pragma unroll
            for (int off = 8; off; off >>= 1)
                tmax = fmaxf(tmax, __shfl_xor_sync(0xffffffffu, tmax, off));
            const float mnew = fmaxf(m_i[i], tmax);
            const float corr = __expf(m_i[i] - mnew);
            float ps = 0.f;
#pragma unroll
            for (int j = 0; j < 4; j++) {
                p[i][j] = __expf(s[i][j] - mnew);
                ps += p[i][j];
            }
#pragma unroll
            for (int off = 8; off; off >>= 1)
                ps += __shfl_xor_sync(0xffffffffu, ps, off);
            l_i[i] = l_i[i] * corr + ps;
            m_i[i] = mnew;
#pragma unroll
            for (int j = 0; j < 4; j++) o[i][j] *= corr;
        }

        __syncthreads();

#pragma unroll
        for (int i = 0; i < 4; i++) {
            float4 pv;
            pv.x = p[i][0]; pv.y = p[i][1]; pv.z = p[i][2]; pv.w = p[i][3];
            *(float4*)&Kbuf[(ty * 4 + i) * 64 + tx * 4] = pv;
        }
        __syncthreads();

#pragma unroll 4
        for (int kk = 0; kk < 64; kk++) {
            float4 v = *(float4*)&Vs[kk * 64 + tx * 4];
#pragma unroll
            for (int i = 0; i < 4; i++) {
                const float pv = Kbuf[(ty * 4 + i) * 64 + kk];
                o[i][0] += pv * v.x;
                o[i][1] += pv * v.y;
                o[i][2] += pv * v.z;
                o[i][3] += pv * v.w;
            }
        }
        __syncthreads();
    }

    float* cbase = Ctx + head_off + (size_t)q0 * DD;
#pragma unroll
    for (int i = 0; i < 4; i++) {
        const float inv_l = 1.0f / l_i[i];
        float4 v;
        v.x = o[i][0] * inv_l;
        v.y = o[i][1] * inv_l;
        v.z = o[i][2] * inv_l;
        v.w = o[i][3] * inv_l;
        *(float4*)&cbase[(size_t)(ty * 4 + i) * DD + tx * 4] = v;
    }
}

// ---------------------------------------------------------------------------
// kernel_launch
// ---------------------------------------------------------------------------
extern "C" void kernel_launch(void* const* d_in, const int* in_sizes, int n_in,
                              void* d_out, int out_size) {
    (void)in_sizes; (void)n_in; (void)out_size;
    const float* x  = (const float*)d_in[0];
    const float* Wq = (const float*)d_in[1];
    const float* Wk = (const float*)d_in[2];
    const float* Wv = (const float*)d_in[3];
    const float* Wo = (const float*)d_in[4];
    const float* bo = (const float*)d_in[5];
    float* out = (float*)d_out;

    float *q, *k, *v, *ctx;
    __nv_bfloat16 *xh, *xl, *ch, *cl, *wh, *wl;
    cudaGetSymbolAddress((void**)&q, g_q);
    cudaGetSymbolAddress((void**)&k, g_k);
    cudaGetSymbolAddress((void**)&v, g_v);
    cudaGetSymbolAddress((void**)&ctx, g_ctx);
    cudaGetSymbolAddress((void**)&xh, g_xh);
    cudaGetSymbolAddress((void**)&xl, g_xl);
    cudaGetSymbolAddress((void**)&ch, g_ch);
    cudaGetSymbolAddress((void**)&cl, g_cl);
    cudaGetSymbolAddress((void**)&wh, g_wh);
    cudaGetSymbolAddress((void**)&wl, g_wl);

    // Prep: split x, transpose+split all 4 weight matrices
    const int n4 = MM * DD / 4;
    cvt_split_kernel<<<(n4 + 255) / 256, 256>>>(x, xh, xl, n4);
    dim3 tgrid(DD / 32, DD / 32), tblk(32, 8);
    wsplit_t_kernel<<<tgrid, tblk>>>(Wq, wh + 0 * DD * DD, wl + 0 * DD * DD);
    wsplit_t_kernel<<<tgrid, tblk>>>(Wk, wh + 1 * DD * DD, wl + 1 * DD * DD);
    wsplit_t_kernel<<<tgrid, tblk>>>(Wv, wh + 2 * DD * DD, wl + 2 * DD * DD);
    wsplit_t_kernel<<<tgrid, tblk>>>(Wo, wh + 3 * DD * DD, wl + 3 * DD * DD);

    // Projections on HMMA (mma.sync bf16 split)
    dim3 ggrid(DD / 128, MM / 128);  // (8, 64)
    gemm_mma<false><<<ggrid, 256, GEMM_SMEM>>>(xh, xl, wh + 0 * DD * DD, wl + 0 * DD * DD, nullptr, q);
    gemm_mma<false><<<ggrid, 256, GEMM_SMEM>>>(xh, xl, wh + 1 * DD * DD, wl + 1 * DD * DD, nullptr, k);
    gemm_mma<false><<<ggrid, 256, GEMM_SMEM>>>(xh, xl, wh + 2 * DD * DD, wl + 2 * DD * DD, nullptr, v);

    // Attention (fp32 FFMA, unchanged)
    dim3 attn_grid(SS / 64, HH, BB);
    attn_kernel<<<attn_grid, 256>>>(q, k, v, ctx);

    // Split ctx, output projection with bias
    cvt_split_kernel<<<(n4 + 255) / 256, 256>>>(ctx, ch, cl, n4);
    gemm_mma<true><<<ggrid, 256, GEMM_SMEM>>>(ch, cl, wh + 3 * DD * DD, wl + 3 * DD * DD, bo, out);
}

// round 5
// speedup vs baseline: 1.2641x; 1.0020x over previous
#include <cuda_runtime.h>
#include <cuda_bf16.h>
#include <cstdint>

// Problem constants
#define BB 4
#define SS 2048
#define DD 1024
#define HH 16
#define HDIM 64
#define MM (BB * SS)   // 8192

// ---------------------------------------------------------------------------
// Static device scratch (no runtime allocation allowed)
// ---------------------------------------------------------------------------
__device__ float g_q[MM * DD];
__device__ float g_k[MM * DD];
__device__ float g_v[MM * DD];
__device__ float g_ctx[MM * DD];

__device__ __nv_bfloat16 g_xh[MM * DD];
__device__ __nv_bfloat16 g_xl[MM * DD];
__device__ __nv_bfloat16 g_ch[MM * DD];
__device__ __nv_bfloat16 g_cl[MM * DD];
__device__ __nv_bfloat16 g_wh[4][DD * DD];  // transposed W hi: [N][K]
__device__ __nv_bfloat16 g_wl[4][DD * DD];  // transposed W lo: [N][K]

// ---------------------------------------------------------------------------
// PTX helpers (arch-agnostic: cp.async + ldmatrix + mma.sync only)
// ---------------------------------------------------------------------------
__device__ __forceinline__ uint32_t smem_u32(const void* p) {
    return (uint32_t)__cvta_generic_to_shared(p);
}

__device__ __forceinline__ void cp16(uint32_t dst, const void* src) {
    asm volatile("cp.async.cg.shared.global [%0], [%1], 16;" :: "r"(dst), "l"(src));
}

__device__ __forceinline__ void ldsm4(uint32_t& r0, uint32_t& r1, uint32_t& r2,
                                      uint32_t& r3, uint32_t addr) {
    asm volatile("ldmatrix.sync.aligned.m8n8.x4.shared.b16 {%0,%1,%2,%3}, [%4];"
                 : "=r"(r0), "=r"(r1), "=r"(r2), "=r"(r3) : "r"(addr));
}

__device__ __forceinline__ void mma_bf16(float c[4], uint32_t a0, uint32_t a1,
                                         uint32_t a2, uint32_t a3,
                                         uint32_t b0, uint32_t b1) {
    asm volatile(
        "mma.sync.aligned.m16n8k16.row.col.f32.bf16.bf16.f32 "
        "{%0,%1,%2,%3}, {%4,%5,%6,%7}, {%8,%9}, {%0,%1,%2,%3};"
        : "+f"(c[0]), "+f"(c[1]), "+f"(c[2]), "+f"(c[3])
        : "r"(a0), "r"(a1), "r"(a2), "r"(a3), "r"(b0), "r"(b1));
}

// ---------------------------------------------------------------------------
// bf16-split HMMA GEMM: C[M,1024] = A[M,1024] @ W^T[N=1024,K] (+bias)
//   A hi/lo bf16 row-major [M,K]; W hi/lo TRANSPOSED [N,K] row-major.
//   C = Ah*Bh + Ah*Bl + Al*Bh, fp32 accumulate in registers.
// CTA tile 128x128, 8 warps (4m x 2n), warp tile 32x64 via m16n8k16.
// K-chunks of 32, double-buffered cp.async.
// ---------------------------------------------------------------------------
#define KC 32
#define ASTRIDE 40                    // bf16 elems per smem row (80B, conflict-free)
#define OP_ELEMS (128 * ASTRIDE)      // per operand per stage
#define NSTG 2
#define NCHUNK 96                     // 3 passes * (1024/32)
#define GEMM_SMEM (NSTG * 2 * OP_ELEMS * 2)  // 40960 bytes

template <bool BIAS>
__global__ __launch_bounds__(256, 2)
void gemm_mma(const __nv_bfloat16* __restrict__ Ah, const __nv_bfloat16* __restrict__ Al,
              const __nv_bfloat16* __restrict__ Bh, const __nv_bfloat16* __restrict__ Bl,
              const float* __restrict__ bias, float* __restrict__ C) {
    extern __shared__ __align__(16) char dyn_smem[];
    __nv_bfloat16* sm = (__nv_bfloat16*)dyn_smem;

    const int tid = threadIdx.x;
    const int wid = tid >> 5;
    const int lane = tid & 31;
    const int wm = (wid & 3) * 32;        // warp m offset within tile
    const int wn = (wid >> 2) * 64;       // warp n offset within tile
    const int m0 = blockIdx.y * 128;
    const int n0 = blockIdx.x * 128;

    float acc[2][8][4];
#pragma unroll
    for (int i = 0; i < 2; i++)
#pragma unroll
        for (int j = 0; j < 8; j++)
#pragma unroll
            for (int t = 0; t < 4; t++) acc[i][j][t] = 0.f;

    // Per-thread load geometry: 2 segments per operand (512 x 16B per operand)
    const int seg0 = tid, seg1 = tid + 256;
    const int r0 = seg0 >> 2, c0 = (seg0 & 3) * 8;
    const int r1 = seg1 >> 2, c1 = (seg1 & 3) * 8;

    auto load_chunk = [&](int c) {
        const int p = c >> 5;          // 0: Ah*Bh, 1: Ah*Bl, 2: Al*Bh
        const int koff = (c & 31) * KC;
        const __nv_bfloat16* Asrc = (p < 2) ? Ah : Al;
        const __nv_bfloat16* Bsrc = (p == 1) ? Bl : Bh;
        __nv_bfloat16* sa = sm + (c & (NSTG - 1)) * 2 * OP_ELEMS;
        __nv_bfloat16* sb = sa + OP_ELEMS;
        cp16(smem_u32(sa + r0 * ASTRIDE + c0), Asrc + (size_t)(m0 + r0) * DD + koff + c0);
        cp16(smem_u32(sa + r1 * ASTRIDE + c1), Asrc + (size_t)(m0 + r1) * DD + koff + c1);
        cp16(smem_u32(sb + r0 * ASTRIDE + c0), Bsrc + (size_t)(n0 + r0) * DD + koff + c0);
        cp16(smem_u32(sb + r1 * ASTRIDE + c1), Bsrc + (size_t)(n0 + r1) * DD + koff + c1);
        asm volatile("cp.async.commit_group;" ::: "memory");
    };

    // ldmatrix lane address components
    const int a_row = lane & 15;            // row within 16-row A tile
    const int a_col = (lane >> 4) * 8;      // k half
    const int b_row = (lane & 7) + ((lane >> 4) << 3);  // n within 16-row pair
    const int b_col = ((lane >> 3) & 1) * 8;            // k half

    load_chunk(0);

    for (int c = 0; c < NCHUNK; c++) {
        if (c + 1 < NCHUNK) {
            load_chunk(c + 1);
            asm volatile("cp.async.wait_group 1;" ::: "memory");
        } else {
            asm volatile("cp.async.wait_group 0;" ::: "memory");
        }
        __syncthreads();

        const __nv_bfloat16* sa = sm + (c & (NSTG - 1)) * 2 * OP_ELEMS;
        const __nv_bfloat16* sb = sa + OP_ELEMS;

#pragma unroll
        for (int ks = 0; ks < 2; ks++) {   // two k16 steps per chunk
            const int k = ks * 16;
            uint32_t a[2][4];
#pragma unroll
            for (int mt = 0; mt < 2; mt++) {
                uint32_t addr = smem_u32(sa + (wm + mt * 16 + a_row) * ASTRIDE + k + a_col);
                ldsm4(a[mt][0], a[mt][1], a[mt][2], a[mt][3], addr);
            }
            uint32_t b[8][2];
#pragma unroll
            for (int np = 0; np < 4; np++) {  // pairs of n8 tiles
                uint32_t addr = smem_u32(sb + (wn + np * 16 + b_row) * ASTRIDE + k + b_col);
                ldsm4(b[2 * np][0], b[2 * np][1], b[2 * np + 1][0], b[2 * np + 1][1], addr);
            }
#pragma unroll
            for (int mt = 0; mt < 2; mt++)
#pragma unroll
                for (int nt = 0; nt < 8; nt++)
                    mma_bf16(acc[mt][nt], a[mt][0], a[mt][1], a[mt][2], a[mt][3],
                             b[nt][0], b[nt][1]);
        }
        __syncthreads();
    }

    // Epilogue: each mma tile: rows lane/4 and lane/4+8, cols 2*(lane%4)+{0,1}
    const int erow = lane >> 2;
    const int ecol = (lane & 3) * 2;
#pragma unroll
    for (int mt = 0; mt < 2; mt++) {
        const int row = m0 + wm + mt * 16 + erow;
#pragma unroll
        for (int nt = 0; nt < 8; nt++) {
            const int col = n0 + wn + nt * 8 + ecol;
            float2 v0, v1;
            v0.x = acc[mt][nt][0]; v0.y = acc[mt][nt][1];
            v1.x = acc[mt][nt][2]; v1.y = acc[mt][nt][3];
            if (BIAS) {
                v0.x += bias[col]; v0.y += bias[col + 1];
                v1.x += bias[col]; v1.y += bias[col + 1];
            }
            *(float2*)&C[(size_t)row * DD + col] = v0;
            *(float2*)&C[(size_t)(row + 8) * DD + col] = v1;
        }
    }
}

// ---------------------------------------------------------------------------
// Prep kernels: fp32 -> (hi, lo) bf16 split; W transpose+split.
// ---------------------------------------------------------------------------
__global__ __launch_bounds__(256)
void cvt_split_kernel(const float* __restrict__ in, __nv_bfloat16* __restrict__ hi,
                      __nv_bfloat16* __restrict__ lo, int n4) {
    int i = blockIdx.x * blockDim.x + threadIdx.x;
    if (i >= n4) return;
    float4 v = ((const float4*)in)[i];
    __nv_bfloat16 h0 = __float2bfloat16(v.x);
    __nv_bfloat16 h1 = __float2bfloat16(v.y);
    __nv_bfloat16 h2 = __float2bfloat16(v.z);
    __nv_bfloat16 h3 = __float2bfloat16(v.w);
    __nv_bfloat162 hp0; hp0.x = h0; hp0.y = h1;
    __nv_bfloat162 hp1; hp1.x = h2; hp1.y = h3;
    __nv_bfloat162 lp0, lp1;
    lp0.x = __float2bfloat16(v.x - __bfloat162float(h0));
    lp0.y = __float2bfloat16(v.y - __bfloat162float(h1));
    lp1.x = __float2bfloat16(v.z - __bfloat162float(h2));
    lp1.y = __float2bfloat16(v.w - __bfloat162float(h3));
    ((__nv_bfloat162*)hi)[2 * i + 0] = hp0;
    ((__nv_bfloat162*)hi)[2 * i + 1] = hp1;
    ((__nv_bfloat162*)lo)[2 * i + 0] = lp0;
    ((__nv_bfloat162*)lo)[2 * i + 1] = lp1;
}

__global__ __launch_bounds__(256)
void wsplit_t_kernel(const float* __restrict__ W, __nv_bfloat16* __restrict__ Th,
                     __nv_bfloat16* __restrict__ Tl) {
    __shared__ float t[32][33];
    const int bx = blockIdx.x * 32;
    const int by = blockIdx.y * 32;
    const int x = bx + threadIdx.x;
#pragma unroll
    for (int j = threadIdx.y; j < 32; j += 8)
        t[j][threadIdx.x] = W[(size_t)(by + j) * DD + x];
    __syncthreads();
    const int xo = by + threadIdx.x;
#pragma unroll
    for (int j = threadIdx.y; j < 32; j += 8) {
        float v = t[threadIdx.x][j];
        __nv_bfloat16 h = __float2bfloat16(v);
        Th[(size_t)(bx + j) * DD + xo] = h;
        Tl[(size_t)(bx + j) * DD + xo] = __float2bfloat16(v - __bfloat162float(h));
    }
}

// ---------------------------------------------------------------------------
// Flash-attention (fp32) — unchanged from the passing baseline.
// ---------------------------------------------------------------------------
__global__ __launch_bounds__(256)
void attn_kernel(const float* __restrict__ Qg, const float* __restrict__ Kg,
                 const float* __restrict__ Vg, float* __restrict__ Ctx) {
    __shared__ float Qs[64 * 64];
    __shared__ float Kbuf[64 * 64];
    __shared__ float Vs[64 * 64];

    const int q0 = blockIdx.x * 64;
    const int h = blockIdx.y;
    const int b = blockIdx.z;
    const int tid = threadIdx.x;
    const int tx = tid & 15;
    const int ty = tid >> 4;
    const int lrow = tid >> 4;
    const int lcol = (tid & 15) * 4;

    const size_t head_off = ((size_t)b * SS) * DD + (size_t)h * HDIM;
    const float* qbase = Qg + head_off + (size_t)q0 * DD;
    const float* kbase = Kg + head_off;
    const float* vbase = Vg + head_off;

#pragma unroll
    for (int r = 0; r < 64; r += 16) {
        *(float4*)&Qs[(r + lrow) * 64 + lcol] =
            *(const float4*)&qbase[(size_t)(r + lrow) * DD + lcol];
    }

    float o[4][4];
    float m_i[4], l_i[4];
#pragma unroll
    for (int i = 0; i < 4; i++) {
        m_i[i] = -1e30f;
        l_i[i] = 0.f;
#pragma unroll
        for (int j = 0; j < 4; j++) o[i][j] = 0.f;
    }

    const int ktiles = min(q0 / 64 + 2, SS / 64);
    __syncthreads();

    for (int t = 0; t < ktiles; t++) {
        const int k0 = t * 64;
        const float* kb = kbase + (size_t)k0 * DD;
        const float* vb = vbase + (size_t)k0 * DD;

#pragma unroll
        for (int r = 0; r < 64; r += 16) {
            const int krow = r + lrow;
            float4 kv = *(const float4*)&kb[(size_t)krow * DD + lcol];
            Kbuf[krow * 64 + ((lcol + 0 + krow) & 63)] = kv.x;
            Kbuf[krow * 64 + ((lcol + 1 + krow) & 63)] = kv.y;
            Kbuf[krow * 64 + ((lcol + 2 + krow) & 63)] = kv.z;
            Kbuf[krow * 64 + ((lcol + 3 + krow) & 63)] = kv.w;
            *(float4*)&Vs[krow * 64 + lcol] =
                *(const float4*)&vb[(size_t)krow * DD + lcol];
        }
        __syncthreads();

        float s[4][4];
#pragma unroll
        for (int i = 0; i < 4; i++)
#pragma unroll
            for (int j = 0; j < 4; j++) s[i][j] = 0.f;

#pragma unroll 8
        for (int d = 0; d < 64; d++) {
            float ra[4], rb[4];
#pragma unroll
            for (int i = 0; i < 4; i++) ra[i] = Qs[(ty * 4 + i) * 64 + d];
#pragma unroll
            for (int j = 0; j < 4; j++) {
                const int kr = tx * 4 + j;
                rb[j] = Kbuf[kr * 64 + ((d + kr) & 63)];
            }
#pragma unroll
            for (int i = 0; i < 4; i++)
#pragma unroll
                for (int j = 0; j < 4; j++) s[i][j] += ra[i] * rb[j];
        }

        const bool need_mask = (k0 >= q0);
#pragma unroll
        for (int i = 0; i < 4; i++)
#pragma unroll
            for (int j = 0; j < 4; j++) {
                s[i][j] *= 0.125f;
                if (need_mask && (k0 + tx * 4 + j > q0 + ty * 4 + i + 1))
                    s[i][j] = -1e30f;
            }

        float p[4][4];
#pragma unroll
        for (int i = 0; i < 4; i++) {
            float tmax = fmaxf(fmaxf(s[i][0], s[i][1]), fmaxf(s[i][2], s[i][3]));
#pragma unroll
            for (int off = 8; off; off >>= 1)
                tmax = fmaxf(tmax, __shfl_xor_sync(0xffffffffu, tmax, off));
            const float mnew = fmaxf(m_i[i], tmax);
            const float corr = __expf(m_i[i] - mnew);
            float ps = 0.f;
#pragma unroll
            for (int j = 0; j < 4; j++) {
                p[i][j] = __expf(s[i][j] - mnew);
                ps += p[i][j];
            }
#pragma unroll
            for (int off = 8; off; off >>= 1)
                ps += __shfl_xor_sync(0xffffffffu, ps, off);
            l_i[i] = l_i[i] * corr + ps;
            m_i[i] = mnew;
#pragma unroll
            for (int j = 0; j < 4; j++) o[i][j] *= corr;
        }

        __syncthreads();

#pragma unroll
        for (int i = 0; i < 4; i++) {
            float4 pv;
            pv.x = p[i][0]; pv.y = p[i][1]; pv.z = p[i][2]; pv.w = p[i][3];
            *(float4*)&Kbuf[(ty * 4 + i) * 64 + tx * 4] = pv;
        }
        __syncthreads();

#pragma unroll 4
        for (int kk = 0; kk < 64; kk++) {
            float4 v = *(float4*)&Vs[kk * 64 + tx * 4];
#pragma unroll
            for (int i = 0; i < 4; i++) {
                const float pv = Kbuf[(ty * 4 + i) * 64 + kk];
                o[i][0] += pv * v.x;
                o[i][1] += pv * v.y;
                o[i][2] += pv * v.z;
                o[i][3] += pv * v.w;
            }
        }
        __syncthreads();
    }

    float* cbase = Ctx + head_off + (size_t)q0 * DD;
#pragma unroll
    for (int i = 0; i < 4; i++) {
        const float inv_l = 1.0f / l_i[i];
        float4 v;
        v.x = o[i][0] * inv_l;
        v.y = o[i][1] * inv_l;
        v.z = o[i][2] * inv_l;
        v.w = o[i][3] * inv_l;
        *(float4*)&cbase[(size_t)(ty * 4 + i) * DD + tx * 4] = v;
    }
}

// ---------------------------------------------------------------------------
// kernel_launch
// ---------------------------------------------------------------------------
extern "C" void kernel_launch(void* const* d_in, const int* in_sizes, int n_in,
                              void* d_out, int out_size) {
    (void)in_sizes; (void)n_in; (void)out_size;
    const float* x  = (const float*)d_in[0];
    const float* Wq = (const float*)d_in[1];
    const float* Wk = (const float*)d_in[2];
    const float* Wv = (const float*)d_in[3];
    const float* Wo = (const float*)d_in[4];
    const float* bo = (const float*)d_in[5];
    float* out = (float*)d_out;

    float *q, *k, *v, *ctx;
    __nv_bfloat16 *xh, *xl, *ch, *cl, *wh, *wl;
    cudaGetSymbolAddress((void**)&q, g_q);
    cudaGetSymbolAddress((void**)&k, g_k);
    cudaGetSymbolAddress((void**)&v, g_v);
    cudaGetSymbolAddress((void**)&ctx, g_ctx);
    cudaGetSymbolAddress((void**)&xh, g_xh);
    cudaGetSymbolAddress((void**)&xl, g_xl);
    cudaGetSymbolAddress((void**)&ch, g_ch);
    cudaGetSymbolAddress((void**)&cl, g_cl);
    cudaGetSymbolAddress((void**)&wh, g_wh);
    cudaGetSymbolAddress((void**)&wl, g_wl);

    // Prep: split x, transpose+split all 4 weight matrices
    const int n4 = MM * DD / 4;
    cvt_split_kernel<<<(n4 + 255) / 256, 256>>>(x, xh, xl, n4);
    dim3 tgrid(DD / 32, DD / 32), tblk(32, 8);
    wsplit_t_kernel<<<tgrid, tblk>>>(Wq, wh + 0 * DD * DD, wl + 0 * DD * DD);
    wsplit_t_kernel<<<tgrid, tblk>>>(Wk, wh + 1 * DD * DD, wl + 1 * DD * DD);
    wsplit_t_kernel<<<tgrid, tblk>>>(Wv, wh + 2 * DD * DD, wl + 2 * DD * DD);
    wsplit_t_kernel<<<tgrid, tblk>>>(Wo, wh + 3 * DD * DD, wl + 3 * DD * DD);

    // Projections on HMMA (mma.sync bf16 split)
    dim3 ggrid(DD / 128, MM / 128);  // (8, 64)
    gemm_mma<false><<<ggrid, 256, GEMM_SMEM>>>(xh, xl, wh + 0 * DD * DD, wl + 0 * DD * DD, nullptr, q);
    gemm_mma<false><<<ggrid, 256, GEMM_SMEM>>>(xh, xl, wh + 1 * DD * DD, wl + 1 * DD * DD, nullptr, k);
    gemm_mma<false><<<ggrid, 256, GEMM_SMEM>>>(xh, xl, wh + 2 * DD * DD, wl + 2 * DD * DD, nullptr, v);

    // Attention (fp32 FFMA, unchanged)
    dim3 attn_grid(SS / 64, HH, BB);
    attn_kernel<<<attn_grid, 256>>>(q, k, v, ctx);

    // Split ctx, output projection with bias
    cvt_split_kernel<<<(n4 + 255) / 256, 256>>>(ctx, ch, cl, n4);
    gemm_mma<true><<<ggrid, 256, GEMM_SMEM>>>(ch, cl, wh + 3 * DD * DD, wl + 3 * DD * DD, bo, out);
}

// round 6
// speedup vs baseline: 1.2714x; 1.0058x over previous
#include <cuda_runtime.h>
#include <cuda_bf16.h>
#include <cstdint>

// Problem constants
#define BB 4
#define SS 2048
#define DD 1024
#define HH 16
#define HDIM 64
#define MM (BB * SS)   // 8192

// ---------------------------------------------------------------------------
// Static device scratch (no runtime allocation allowed)
// ---------------------------------------------------------------------------
__device__ float g_q[MM * DD];
__device__ float g_k[MM * DD];
__device__ float g_v[MM * DD];
__device__ float g_ctx[MM * DD];

__device__ __nv_bfloat16 g_xh[MM * DD];
__device__ __nv_bfloat16 g_xl[MM * DD];
__device__ __nv_bfloat16 g_ch[MM * DD];
__device__ __nv_bfloat16 g_cl[MM * DD];
__device__ __nv_bfloat16 g_wh[4][DD * DD];  // transposed W hi: [N][K]
__device__ __nv_bfloat16 g_wl[4][DD * DD];  // transposed W lo: [N][K]

// ---------------------------------------------------------------------------
// PTX helpers (arch-agnostic: cp.async + ldmatrix + mma.sync only)
// ---------------------------------------------------------------------------
__device__ __forceinline__ uint32_t smem_u32(const void* p) {
    return (uint32_t)__cvta_generic_to_shared(p);
}

__device__ __forceinline__ void cp16(uint32_t dst, const void* src) {
    asm volatile("cp.async.cg.shared.global [%0], [%1], 16;" :: "r"(dst), "l"(src));
}

__device__ __forceinline__ void ldsm4(uint32_t& r0, uint32_t& r1, uint32_t& r2,
                                      uint32_t& r3, uint32_t addr) {
    asm volatile("ldmatrix.sync.aligned.m8n8.x4.shared.b16 {%0,%1,%2,%3}, [%4];"
                 : "=r"(r0), "=r"(r1), "=r"(r2), "=r"(r3) : "r"(addr));
}

__device__ __forceinline__ void mma_bf16(float c[4], uint32_t a0, uint32_t a1,
                                         uint32_t a2, uint32_t a3,
                                         uint32_t b0, uint32_t b1) {
    asm volatile(
        "mma.sync.aligned.m16n8k16.row.col.f32.bf16.bf16.f32 "
        "{%0,%1,%2,%3}, {%4,%5,%6,%7}, {%8,%9}, {%0,%1,%2,%3};"
        : "+f"(c[0]), "+f"(c[1]), "+f"(c[2]), "+f"(c[3])
        : "r"(a0), "r"(a1), "r"(a2), "r"(a3), "r"(b0), "r"(b1));
}

// ---------------------------------------------------------------------------
// bf16-split HMMA GEMM: C[M,1024] = A[M,1024] @ W^T[N=1024,K] (+bias)
//   A hi/lo bf16 row-major [M,K]; W hi/lo TRANSPOSED [N,K] row-major.
//   C = Ah*Bh + Ah*Bl + Al*Bh, fp32 accumulate in registers.
// CTA tile 128x128, 8 warps (4m x 2n), warp tile 32x64 via m16n8k16.
// K-chunks of 32, double-buffered cp.async.
// ---------------------------------------------------------------------------
#define KC 32
#define ASTRIDE 40                    // bf16 elems per smem row (80B, conflict-free)
#define OP_ELEMS (128 * ASTRIDE)      // per operand per stage
#define NSTG 2
#define NCHUNK 96                     // 3 passes * (1024/32)
#define GEMM_SMEM (NSTG * 2 * OP_ELEMS * 2)  // 40960 bytes

template <bool BIAS>
__global__ __launch_bounds__(256, 2)
void gemm_mma(const __nv_bfloat16* __restrict__ Ah, const __nv_bfloat16* __restrict__ Al,
              const __nv_bfloat16* __restrict__ Bh, const __nv_bfloat16* __restrict__ Bl,
              const float* __restrict__ bias, float* __restrict__ C) {
    extern __shared__ __align__(16) char dyn_smem[];
    __nv_bfloat16* sm = (__nv_bfloat16*)dyn_smem;

    const int tid = threadIdx.x;
    const int wid = tid >> 5;
    const int lane = tid & 31;
    const int wm = (wid & 3) * 32;        // warp m offset within tile
    const int wn = (wid >> 2) * 64;       // warp n offset within tile
    const int m0 = blockIdx.y * 128;
    const int n0 = blockIdx.x * 128;

    float acc[2][8][4];
#pragma unroll
    for (int i = 0; i < 2; i++)
#pragma unroll
        for (int j = 0; j < 8; j++)
#pragma unroll
            for (int t = 0; t < 4; t++) acc[i][j][t] = 0.f;

    // Per-thread load geometry: 2 segments per operand (512 x 16B per operand)
    const int seg0 = tid, seg1 = tid + 256;
    const int r0 = seg0 >> 2, c0 = (seg0 & 3) * 8;
    const int r1 = seg1 >> 2, c1 = (seg1 & 3) * 8;

    auto load_chunk = [&](int c) {
        const int p = c >> 5;          // 0: Ah*Bh, 1: Ah*Bl, 2: Al*Bh
        const int koff = (c & 31) * KC;
        const __nv_bfloat16* Asrc = (p < 2) ? Ah : Al;
        const __nv_bfloat16* Bsrc = (p == 1) ? Bl : Bh;
        __nv_bfloat16* sa = sm + (c & (NSTG - 1)) * 2 * OP_ELEMS;
        __nv_bfloat16* sb = sa + OP_ELEMS;
        cp16(smem_u32(sa + r0 * ASTRIDE + c0), Asrc + (size_t)(m0 + r0) * DD + koff + c0);
        cp16(smem_u32(sa + r1 * ASTRIDE + c1), Asrc + (size_t)(m0 + r1) * DD + koff + c1);
        cp16(smem_u32(sb + r0 * ASTRIDE + c0), Bsrc + (size_t)(n0 + r0) * DD + koff + c0);
        cp16(smem_u32(sb + r1 * ASTRIDE + c1), Bsrc + (size_t)(n0 + r1) * DD + koff + c1);
        asm volatile("cp.async.commit_group;" ::: "memory");
    };

    // ldmatrix lane address components
    const int a_row = lane & 15;            // row within 16-row A tile
    const int a_col = (lane >> 4) * 8;      // k half
    const int b_row = (lane & 7) + ((lane >> 4) << 3);  // n within 16-row pair
    const int b_col = ((lane >> 3) & 1) * 8;            // k half

    load_chunk(0);

    for (int c = 0; c < NCHUNK; c++) {
        if (c + 1 < NCHUNK) {
            load_chunk(c + 1);
            asm volatile("cp.async.wait_group 1;" ::: "memory");
        } else {
            asm volatile("cp.async.wait_group 0;" ::: "memory");
        }
        __syncthreads();

        const __nv_bfloat16* sa = sm + (c & (NSTG - 1)) * 2 * OP_ELEMS;
        const __nv_bfloat16* sb = sa + OP_ELEMS;

#pragma unroll
        for (int ks = 0; ks < 2; ks++) {   // two k16 steps per chunk
            const int k = ks * 16;
            uint32_t a[2][4];
#pragma unroll
            for (int mt = 0; mt < 2; mt++) {
                uint32_t addr = smem_u32(sa + (wm + mt * 16 + a_row) * ASTRIDE + k + a_col);
                ldsm4(a[mt][0], a[mt][1], a[mt][2], a[mt][3], addr);
            }
            uint32_t b[8][2];
#pragma unroll
            for (int np = 0; np < 4; np++) {  // pairs of n8 tiles
                uint32_t addr = smem_u32(sb + (wn + np * 16 + b_row) * ASTRIDE + k + b_col);
                ldsm4(b[2 * np][0], b[2 * np][1], b[2 * np + 1][0], b[2 * np + 1][1], addr);
            }
#pragma unroll
            for (int mt = 0; mt < 2; mt++)
#pragma unroll
                for (int nt = 0; nt < 8; nt++)
                    mma_bf16(acc[mt][nt], a[mt][0], a[mt][1], a[mt][2], a[mt][3],
                             b[nt][0], b[nt][1]);
        }
        __syncthreads();
    }

    // Epilogue: each mma tile: rows lane/4 and lane/4+8, cols 2*(lane%4)+{0,1}
    const int erow = lane >> 2;
    const int ecol = (lane & 3) * 2;
#pragma unroll
    for (int mt = 0; mt < 2; mt++) {
        const int row = m0 + wm + mt * 16 + erow;
#pragma unroll
        for (int nt = 0; nt < 8; nt++) {
            const int col = n0 + wn + nt * 8 + ecol;
            float2 v0, v1;
            v0.x = acc[mt][nt][0]; v0.y = acc[mt][nt][1];
            v1.x = acc[mt][nt][2]; v1.y = acc[mt][nt][3];
            if (BIAS) {
                v0.x += bias[col]; v0.y += bias[col + 1];
                v1.x += bias[col]; v1.y += bias[col + 1];
            }
            *(float2*)&C[(size_t)row * DD + col] = v0;
            *(float2*)&C[(size_t)(row + 8) * DD + col] = v1;
        }
    }
}

// ---------------------------------------------------------------------------
// Prep kernels: fp32 -> (hi, lo) bf16 split; W transpose+split.
// ---------------------------------------------------------------------------
__global__ __launch_bounds__(256)
void cvt_split_kernel(const float* __restrict__ in, __nv_bfloat16* __restrict__ hi,
                      __nv_bfloat16* __restrict__ lo, int n4) {
    int i = blockIdx.x * blockDim.x + threadIdx.x;
    if (i >= n4) return;
    float4 v = ((const float4*)in)[i];
    __nv_bfloat16 h0 = __float2bfloat16(v.x);
    __nv_bfloat16 h1 = __float2bfloat16(v.y);
    __nv_bfloat16 h2 = __float2bfloat16(v.z);
    __nv_bfloat16 h3 = __float2bfloat16(v.w);
    __nv_bfloat162 hp0; hp0.x = h0; hp0.y = h1;
    __nv_bfloat162 hp1; hp1.x = h2; hp1.y = h3;
    __nv_bfloat162 lp0, lp1;
    lp0.x = __float2bfloat16(v.x - __bfloat162float(h0));
    lp0.y = __float2bfloat16(v.y - __bfloat162float(h1));
    lp1.x = __float2bfloat16(v.z - __bfloat162float(h2));
    lp1.y = __float2bfloat16(v.w - __bfloat162float(h3));
    ((__nv_bfloat162*)hi)[2 * i + 0] = hp0;
    ((__nv_bfloat162*)hi)[2 * i + 1] = hp1;
    ((__nv_bfloat162*)lo)[2 * i + 0] = lp0;
    ((__nv_bfloat162*)lo)[2 * i + 1] = lp1;
}

__global__ __launch_bounds__(256)
void wsplit_t_kernel(const float* __restrict__ W, __nv_bfloat16* __restrict__ Th,
                     __nv_bfloat16* __restrict__ Tl) {
    __shared__ float t[32][33];
    const int bx = blockIdx.x * 32;
    const int by = blockIdx.y * 32;
    const int x = bx + threadIdx.x;
#pragma unroll
    for (int j = threadIdx.y; j < 32; j += 8)
        t[j][threadIdx.x] = W[(size_t)(by + j) * DD + x];
    __syncthreads();
    const int xo = by + threadIdx.x;
#pragma unroll
    for (int j = threadIdx.y; j < 32; j += 8) {
        float v = t[threadIdx.x][j];
        __nv_bfloat16 h = __float2bfloat16(v);
        Th[(size_t)(bx + j) * DD + xo] = h;
        Tl[(size_t)(bx + j) * DD + xo] = __float2bfloat16(v - __bfloat162float(h));
    }
}

// ---------------------------------------------------------------------------
// Flash-attention (fp32) — unchanged from the passing baseline.
// ---------------------------------------------------------------------------
__global__ __launch_bounds__(256)
void attn_kernel(const float* __restrict__ Qg, const float* __restrict__ Kg,
                 const float* __restrict__ Vg, float* __restrict__ Ctx) {
    __shared__ float Qs[64 * 64];
    __shared__ float Kbuf[64 * 64];
    __shared__ float Vs[64 * 64];

    const int q0 = blockIdx.x * 64;
    const int h = blockIdx.y;
    const int b = blockIdx.z;
    const int tid = threadIdx.x;
    const int tx = tid & 15;
    const int ty = tid >> 4;
    const int lrow = tid >> 4;
    const int lcol = (tid & 15) * 4;

    const size_t head_off = ((size_t)b * SS) * DD + (size_t)h * HDIM;
    const float* qbase = Qg + head_off + (size_t)q0 * DD;
    const float* kbase = Kg + head_off;
    const float* vbase = Vg + head_off;

#pragma unroll
    for (int r = 0; r < 64; r += 16) {
        *(float4*)&Qs[(r + lrow) * 64 + lcol] =
            *(const float4*)&qbase[(size_t)(r + lrow) * DD + lcol];
    }

    float o[4][4];
    float m_i[4], l_i[4];
#pragma unroll
    for (int i = 0; i < 4; i++) {
        m_i[i] = -1e30f;
        l_i[i] = 0.f;
#pragma unroll
        for (int j = 0; j < 4; j++) o[i][j] = 0.f;
    }

    const int ktiles = min(q0 / 64 + 2, SS / 64);
    __syncthreads();

    for (int t = 0; t < ktiles; t++) {
        const int k0 = t * 64;
        const float* kb = kbase + (size_t)k0 * DD;
        const float* vb = vbase + (size_t)k0 * DD;

#pragma unroll
        for (int r = 0; r < 64; r += 16) {
            const int krow = r + lrow;
            float4 kv = *(const float4*)&kb[(size_t)krow * DD + lcol];
            Kbuf[krow * 64 + ((lcol + 0 + krow) & 63)] = kv.x;
            Kbuf[krow * 64 + ((lcol + 1 + krow) & 63)] = kv.y;
            Kbuf[krow * 64 + ((lcol + 2 + krow) & 63)] = kv.z;
            Kbuf[krow * 64 + ((lcol + 3 + krow) & 63)] = kv.w;
            *(float4*)&Vs[krow * 64 + lcol] =
                *(const float4*)&vb[(size_t)krow * DD + lcol];
        }
        __syncthreads();

        float s[4][4];
#pragma unroll
        for (int i = 0; i < 4; i++)
#pragma unroll
            for (int j = 0; j < 4; j++) s[i][j] = 0.f;

#pragma unroll 8
        for (int d = 0; d < 64; d++) {
            float ra[4], rb[4];
#pragma unroll
            for (int i = 0; i < 4; i++) ra[i] = Qs[(ty * 4 + i) * 64 + d];
#pragma unroll
            for (int j = 0; j < 4; j++) {
                const int kr = tx * 4 + j;
                rb[j] = Kbuf[kr * 64 + ((d + kr) & 63)];
            }
#pragma unroll
            for (int i = 0; i < 4; i++)
#pragma unroll
                for (int j = 0; j < 4; j++) s[i][j] += ra[i] * rb[j];
        }

        const bool need_mask = (k0 >= q0);
#pragma unroll
        for (int i = 0; i < 4; i++)
#pragma unroll
            for (int j = 0; j < 4; j++) {
                s[i][j] *= 0.125f;
                if (need_mask && (k0 + tx * 4 + j > q0 + ty * 4 + i + 1))
                    s[i][j] = -1e30f;
            }

        float p[4][4];
#pragma unroll
        for (int i = 0; i < 4; i++) {
            float tmax = fmaxf(fmaxf(s[i][0], s[i][1]), fmaxf(s[i][2], s[i][3]));
#pragma unroll
            for (int off = 8; off; off >>= 1)
                tmax = fmaxf(tmax, __shfl_xor_sync(0xffffffffu, tmax, off));
            const float mnew = fmaxf(m_i[i], tmax);
            const float corr = __expf(m_i[i] - mnew);
            float ps = 0.f;
#pragma unroll
            for (int j = 0; j < 4; j++) {
                p[i][j] = __expf(s[i][j] - mnew);
                ps += p[i][j];
            }
#pragma unroll
            for (int off = 8; off; off >>= 1)
                ps += __shfl_xor_sync(0xffffffffu, ps, off);
            l_i[i] = l_i[i] * corr + ps;
            m_i[i] = mnew;
#pragma unroll
            for (int j = 0; j < 4; j++) o[i][j] *= corr;
        }

        __syncthreads();

#pragma unroll
        for (int i = 0; i < 4; i++) {
            float4 pv;
            pv.x = p[i][0]; pv.y = p[i][1]; pv.z = p[i][2]; pv.w = p[i][3];
            *(float4*)&Kbuf[(ty * 4 + i) * 64 + tx * 4] = pv;
        }
        __syncthreads();

#pragma unroll 4
        for (int kk = 0; kk < 64; kk++) {
            float4 v = *(float4*)&Vs[kk * 64 + tx * 4];
#pragma unroll
            for (int i = 0; i < 4; i++) {
                const float pv = Kbuf[(ty * 4 + i) * 64 + kk];
                o[i][0] += pv * v.x;
                o[i][1] += pv * v.y;
                o[i][2] += pv * v.z;
                o[i][3] += pv * v.w;
            }
        }
        __syncthreads();
    }

    float* cbase = Ctx + head_off + (size_t)q0 * DD;
#pragma unroll
    for (int i = 0; i < 4; i++) {
        const float inv_l = 1.0f / l_i[i];
        float4 v;
        v.x = o[i][0] * inv_l;
        v.y = o[i][1] * inv_l;
        v.z = o[i][2] * inv_l;
        v.w = o[i][3] * inv_l;
        *(float4*)&cbase[(size_t)(ty * 4 + i) * DD + tx * 4] = v;
    }
}

// ---------------------------------------------------------------------------
// kernel_launch
// ---------------------------------------------------------------------------
extern "C" void kernel_launch(void* const* d_in, const int* in_sizes, int n_in,
                              void* d_out, int out_size) {
    (void)in_sizes; (void)n_in; (void)out_size;
    const float* x  = (const float*)d_in[0];
    const float* Wq = (const float*)d_in[1];
    const float* Wk = (const float*)d_in[2];
    const float* Wv = (const float*)d_in[3];
    const float* Wo = (const float*)d_in[4];
    const float* bo = (const float*)d_in[5];
    float* out = (float*)d_out;

    float *q, *k, *v, *ctx;
    __nv_bfloat16 *xh, *xl, *ch, *cl, *wh, *wl;
    cudaGetSymbolAddress((void**)&q, g_q);
    cudaGetSymbolAddress((void**)&k, g_k);
    cudaGetSymbolAddress((void**)&v, g_v);
    cudaGetSymbolAddress((void**)&ctx, g_ctx);
    cudaGetSymbolAddress((void**)&xh, g_xh);
    cudaGetSymbolAddress((void**)&xl, g_xl);
    cudaGetSymbolAddress((void**)&ch, g_ch);
    cudaGetSymbolAddress((void**)&cl, g_cl);
    cudaGetSymbolAddress((void**)&wh, g_wh);
    cudaGetSymbolAddress((void**)&wl, g_wl);

    // Prep: split x, transpose+split all 4 weight matrices
    const int n4 = MM * DD / 4;
    cvt_split_kernel<<<(n4 + 255) / 256, 256>>>(x, xh, xl, n4);
    dim3 tgrid(DD / 32, DD / 32), tblk(32, 8);
    wsplit_t_kernel<<<tgrid, tblk>>>(Wq, wh + 0 * DD * DD, wl + 0 * DD * DD);
    wsplit_t_kernel<<<tgrid, tblk>>>(Wk, wh + 1 * DD * DD, wl + 1 * DD * DD);
    wsplit_t_kernel<<<tgrid, tblk>>>(Wv, wh + 2 * DD * DD, wl + 2 * DD * DD);
    wsplit_t_kernel<<<tgrid, tblk>>>(Wo, wh + 3 * DD * DD, wl + 3 * DD * DD);

    // Projections on HMMA (mma.sync bf16 split)
    dim3 ggrid(DD / 128, MM / 128);  // (8, 64)
    gemm_mma<false><<<ggrid, 256, GEMM_SMEM>>>(xh, xl, wh + 0 * DD * DD, wl + 0 * DD * DD, nullptr, q);
    gemm_mma<false><<<ggrid, 256, GEMM_SMEM>>>(xh, xl, wh + 1 * DD * DD, wl + 1 * DD * DD, nullptr, k);
    gemm_mma<false><<<ggrid, 256, GEMM_SMEM>>>(xh, xl, wh + 2 * DD * DD, wl + 2 * DD * DD, nullptr, v);

    // Attention (fp32 FFMA, unchanged)
    dim3 attn_grid(SS / 64, HH, BB);
    attn_kernel<<<attn_grid, 256>>>(q, k, v, ctx);

    // Split ctx, output projection with bias
    cvt_split_kernel<<<(n4 + 255) / 256, 256>>>(ctx, ch, cl, n4);
    gemm_mma<true><<<ggrid, 256, GEMM_SMEM>>>(ch, cl, wh + 3 * DD * DD, wl + 3 * DD * DD, bo, out);
}